// round 5
// baseline (speedup 1.0000x reference)
#include <cuda_runtime.h>
#include <cuda_bf16.h>
#include <cstdint>
#include <cstddef>

// Problem constants
#define BATCH 2
#define SEQ 2048
#define HID 2048
#define KVSZ 512
#define HEADS 32
#define HD 64
#define MTOK (BATCH*SEQ)   // 4096 rows

// ---------------------------------------------------------------------------
// Scratch (device globals: allocation-free)
// ---------------------------------------------------------------------------
__device__ float g_q[(size_t)MTOK * HID];
__device__ float g_k[(size_t)MTOK * KVSZ];
__device__ float g_v[(size_t)MTOK * KVSZ];
__device__ float g_ao[(size_t)MTOK * HID];

__device__ __nv_bfloat16 g_xh[(size_t)MTOK * HID];
__device__ __nv_bfloat16 g_xl[(size_t)MTOK * HID];
__device__ __nv_bfloat16 g_aoh[(size_t)MTOK * HID];
__device__ __nv_bfloat16 g_aol[(size_t)MTOK * HID];
// transposed weights [N, K] bf16 hi/lo
__device__ __nv_bfloat16 g_wqh[(size_t)HID * HID];
__device__ __nv_bfloat16 g_wql[(size_t)HID * HID];
__device__ __nv_bfloat16 g_wkh[(size_t)KVSZ * HID];
__device__ __nv_bfloat16 g_wkl[(size_t)KVSZ * HID];
__device__ __nv_bfloat16 g_wvh[(size_t)KVSZ * HID];
__device__ __nv_bfloat16 g_wvl[(size_t)KVSZ * HID];
__device__ __nv_bfloat16 g_woh[(size_t)HID * HID];
__device__ __nv_bfloat16 g_wol[(size_t)HID * HID];

// ---------------------------------------------------------------------------
// Portable PTX helpers (no sm_103a-gated instructions!)
// ---------------------------------------------------------------------------
static __device__ __forceinline__ uint32_t smem_u32(const void* p) {
    uint32_t a;
    asm("{ .reg .u64 t; cvta.to.shared.u64 t, %1; cvt.u32.u64 %0, t; }" : "=r"(a) : "l"(p));
    return a;
}
static __device__ __forceinline__ void cp16(uint32_t dst, const void* src) {
    asm volatile("cp.async.cg.shared.global [%0], [%1], 16;" :: "r"(dst), "l"(src));
}
static __device__ __forceinline__ void ldsm4(uint32_t& r0, uint32_t& r1, uint32_t& r2,
                                             uint32_t& r3, uint32_t addr) {
    asm volatile("ldmatrix.sync.aligned.m8n8.x4.shared.b16 {%0,%1,%2,%3}, [%4];"
                 : "=r"(r0), "=r"(r1), "=r"(r2), "=r"(r3) : "r"(addr));
}
static __device__ __forceinline__ void mma16816(float* c, const uint32_t* a,
                                                const uint32_t* b) {
    asm volatile(
        "mma.sync.aligned.m16n8k16.row.col.f32.bf16.bf16.f32 "
        "{%0,%1,%2,%3}, {%4,%5,%6,%7}, {%8,%9}, {%0,%1,%2,%3};"
        : "+f"(c[0]), "+f"(c[1]), "+f"(c[2]), "+f"(c[3])
        : "r"(a[0]), "r"(a[1]), "r"(a[2]), "r"(a[3]), "r"(b[0]), "r"(b[1]));
}

// ---------------------------------------------------------------------------
// Split conversions: fp32 -> (hi, lo) bf16
// ---------------------------------------------------------------------------
__global__ void __launch_bounds__(256)
split_hl(const float* __restrict__ in, __nv_bfloat16* __restrict__ hi,
         __nv_bfloat16* __restrict__ lo, int n) {
    int i = (blockIdx.x * 256 + threadIdx.x) << 2;
    if (i >= n) return;
    float4 f = *(const float4*)(in + i);
    __nv_bfloat16 h0 = __float2bfloat16(f.x);
    __nv_bfloat16 h1 = __float2bfloat16(f.y);
    __nv_bfloat16 h2 = __float2bfloat16(f.z);
    __nv_bfloat16 h3 = __float2bfloat16(f.w);
    __nv_bfloat16 l0 = __float2bfloat16(f.x - __bfloat162float(h0));
    __nv_bfloat16 l1 = __float2bfloat16(f.y - __bfloat162float(h1));
    __nv_bfloat16 l2 = __float2bfloat16(f.z - __bfloat162float(h2));
    __nv_bfloat16 l3 = __float2bfloat16(f.w - __bfloat162float(h3));
    ushort4 uh = make_ushort4(__bfloat16_as_ushort(h0), __bfloat16_as_ushort(h1),
                              __bfloat16_as_ushort(h2), __bfloat16_as_ushort(h3));
    ushort4 ul = make_ushort4(__bfloat16_as_ushort(l0), __bfloat16_as_ushort(l1),
                              __bfloat16_as_ushort(l2), __bfloat16_as_ushort(l3));
    *(ushort4*)(hi + i) = uh;
    *(ushort4*)(lo + i) = ul;
}

// W [Kd, Nd] fp32 row-major -> th/tl [Nd, Kd] bf16 (transposed)
__global__ void __launch_bounds__(256)
split_transpose(const float* __restrict__ W, __nv_bfloat16* __restrict__ th,
                __nv_bfloat16* __restrict__ tl, int Kd, int Nd) {
    __shared__ float t[32][33];
    int n0 = blockIdx.x << 5, k0 = blockIdx.y << 5;
    int tx = threadIdx.x & 31, ty = threadIdx.x >> 5;  // ty 0..7
#pragma unroll
    for (int r = 0; r < 32; r += 8)
        t[ty + r][tx] = W[(size_t)(k0 + ty + r) * Nd + n0 + tx];
    __syncthreads();
#pragma unroll
    for (int r = 0; r < 32; r += 8) {
        float f = t[tx][ty + r];
        __nv_bfloat16 h = __float2bfloat16(f);
        __nv_bfloat16 l = __float2bfloat16(f - __bfloat162float(h));
        size_t o = (size_t)(n0 + ty + r) * Kd + k0 + tx;
        th[o] = h;
        tl[o] = l;
    }
}

// ---------------------------------------------------------------------------
// HMMA GEMM: C[M,N] = Ah@Bh^T + Ah@Bl^T + Al@Bh^T + bias  (fp32 out)
// A* [M,K] bf16 row-major; B* [N,K] bf16 row-major (W transposed).
// CTA tile 128x128, BK=32, 8 warps (each 64x32), cp.async double buffer.
// Smem rows padded to 80B (32 bf16 + 16B) -> conflict-free ldmatrix.
// ---------------------------------------------------------------------------
#define GBM 128
#define GBN 128
#define ROWB 80                         // bytes per smem row
#define TILEB (128 * ROWB)              // 10240 per matrix tile
#define STAGEB (2 * TILEB)              // A + B per stage

__global__ void __launch_bounds__(256)
gemm_mma(const __nv_bfloat16* __restrict__ Ah, const __nv_bfloat16* __restrict__ Al,
         const __nv_bfloat16* __restrict__ Bh, const __nv_bfloat16* __restrict__ Bl,
         const float* __restrict__ bias, float* __restrict__ C,
         int M, int N, int K)
{
    __shared__ __align__(16) char smem[2 * STAGEB];
    const uint32_t sb = smem_u32(smem);

    const int tid  = threadIdx.x;
    const int wid  = tid >> 5;
    const int lane = tid & 31;
    const int warp_m = (wid & 1) << 6;   // 0 / 64
    const int warp_n = (wid >> 1) << 5;  // 0 / 32 / 64 / 96

    const int row0 = blockIdx.y * GBM;
    const int col0 = blockIdx.x * GBN;

    const int KS = K >> 5;               // k-slabs per pass
    const int NS = 3 * KS;

    // cp.async mapping: 512 A-chunks + 512 B-chunks of 16B, 2 each per thread
    const int c_r  = tid >> 1;           // row 0..127
    const int c_c0 = (tid & 1) << 1;     // chunk 0 or 2

    // ldmatrix per-thread offsets
    const uint32_t a_off = (uint32_t)((warp_m + (lane & 7) + (((lane >> 3) & 1) << 3)) * ROWB
                                      + ((lane >> 4) << 4));            // +16B for k-half
    const uint32_t b_off = (uint32_t)((warp_n + (lane & 7) + ((lane >> 4) << 3)) * ROWB
                                      + (((lane >> 3) & 1) << 4));

    float acc[4][4][4];
#pragma unroll
    for (int i = 0; i < 4; i++)
#pragma unroll
        for (int j = 0; j < 4; j++)
#pragma unroll
            for (int t = 0; t < 4; t++) acc[i][j][t] = 0.f;

    // ---- stage loader ------------------------------------------------------
    auto load_stage = [&](int i, int s) {
        int p  = (i >= 2 * KS) ? 2 : ((i >= KS) ? 1 : 0);
        int kk = (i - p * KS) << 5;
        const __nv_bfloat16* Ag = ((p == 2) ? Al : Ah) + (size_t)row0 * K + kk;
        const __nv_bfloat16* Bg = ((p == 1) ? Bl : Bh) + (size_t)col0 * K + kk;
        uint32_t sa = sb + (uint32_t)s * STAGEB;
        uint32_t sbB = sa + TILEB;
        size_t rowbytes = (size_t)K * 2;
        const char* agc = (const char*)Ag + (size_t)c_r * rowbytes;
        const char* bgc = (const char*)Bg + (size_t)c_r * rowbytes;
        uint32_t so = (uint32_t)(c_r * ROWB + c_c0 * 16);
        cp16(sa  + so,      agc + c_c0 * 16);
        cp16(sa  + so + 16, agc + c_c0 * 16 + 16);
        cp16(sbB + so,      bgc + c_c0 * 16);
        cp16(sbB + so + 16, bgc + c_c0 * 16 + 16);
        asm volatile("cp.async.commit_group;" ::: "memory");
    };

    load_stage(0, 0);

    for (int i = 0; i < NS; i++) {
        int s = i & 1;
        if (i + 1 < NS) {
            load_stage(i + 1, s ^ 1);
            asm volatile("cp.async.wait_group 1;" ::: "memory");
        } else {
            asm volatile("cp.async.wait_group 0;" ::: "memory");
        }
        __syncthreads();

        uint32_t sa  = sb + (uint32_t)s * STAGEB;
        uint32_t sbB = sa + TILEB;
#pragma unroll
        for (int ks = 0; ks < 2; ks++) {          // two k16 steps per BK=32
            uint32_t kb = (uint32_t)(ks << 5);    // 16 halves = 32 bytes
            uint32_t a[4][4], b[4][2];
#pragma unroll
            for (int mt = 0; mt < 4; mt++)
                ldsm4(a[mt][0], a[mt][1], a[mt][2], a[mt][3],
                      sa + a_off + (uint32_t)(mt << 4) * ROWB + kb);
#pragma unroll
            for (int np = 0; np < 2; np++)
                ldsm4(b[2*np][0], b[2*np][1], b[2*np+1][0], b[2*np+1][1],
                      sbB + b_off + (uint32_t)(np << 4) * ROWB + kb);
#pragma unroll
            for (int mt = 0; mt < 4; mt++)
#pragma unroll
                for (int nt = 0; nt < 4; nt++)
                    mma16816(acc[mt][nt], a[mt], b[nt]);
        }
        __syncthreads();
    }

    // ---- epilogue -----------------------------------------------------------
    const int qr = lane >> 2;            // quad row 0..7
    const int qc = (lane & 3) << 1;      // col pair 0,2,4,6
#pragma unroll
    for (int mt = 0; mt < 4; mt++) {
        int r = row0 + warp_m + (mt << 4) + qr;
        float* C0 = C + (size_t)r * N;
        float* C1 = C + (size_t)(r + 8) * N;
#pragma unroll
        for (int nt = 0; nt < 4; nt++) {
            int c = col0 + warp_n + (nt << 3) + qc;
            float b0 = bias[c], b1 = bias[c + 1];
            float2 v0 = make_float2(acc[mt][nt][0] + b0, acc[mt][nt][1] + b1);
            float2 v1 = make_float2(acc[mt][nt][2] + b0, acc[mt][nt][3] + b1);
            *(float2*)(C0 + c) = v0;
            *(float2*)(C1 + c) = v1;
        }
    }
}

// ---------------------------------------------------------------------------
// Flash attention, fp32 (unchanged — passing at rel_err 1.9e-6)
// ---------------------------------------------------------------------------
__global__ __launch_bounds__(128, 2)
void flash_attn(const float* __restrict__ q, const float* __restrict__ k,
                const float* __restrict__ v, const float* __restrict__ mask,
                float* __restrict__ out) {
    const int BN = 64;
    int h = blockIdx.y;
    int b = blockIdx.z;
    int r = blockIdx.x * 128 + threadIdx.x;
    int qcol = h * HD;
    int kcol = (h >> 2) * HD;

    const float scale = 0.125f;
    float qr[HD];
    {
        const float* qrow = q + ((size_t)b * SEQ + r) * HID + qcol;
#pragma unroll
        for (int d = 0; d < HD; d++) qr[d] = qrow[d] * scale;
    }

    float m = -1e30f, l = 0.f;
    float acc[HD];
#pragma unroll
    for (int d = 0; d < HD; d++) acc[d] = 0.f;

    __shared__ float ks[BN][HD];
    __shared__ float vs[BN][HD];
    __shared__ float ms[BN];

    const float* kbase = k + (size_t)b * SEQ * KVSZ + kcol;
    const float* vbase = v + (size_t)b * SEQ * KVSZ + kcol;
    const float* mbase = mask + (size_t)b * SEQ;

    for (int kt = 0; kt < SEQ; kt += BN) {
        __syncthreads();
        for (int i = threadIdx.x; i < BN * (HD / 4); i += 128) {
            int j  = i >> 4;
            int d4 = (i & 15) << 2;
            *(float4*)&ks[j][d4] = *(const float4*)&kbase[(size_t)(kt + j) * KVSZ + d4];
            *(float4*)&vs[j][d4] = *(const float4*)&vbase[(size_t)(kt + j) * KVSZ + d4];
        }
        if (threadIdx.x < BN) ms[threadIdx.x] = mbase[kt + threadIdx.x];
        __syncthreads();

        for (int j = 0; j < BN; j++) {
            float s0 = 0.f, s1 = 0.f, s2 = 0.f, s3 = 0.f;
#pragma unroll
            for (int d = 0; d < HD; d += 4) {
                s0 += qr[d + 0] * ks[j][d + 0];
                s1 += qr[d + 1] * ks[j][d + 1];
                s2 += qr[d + 2] * ks[j][d + 2];
                s3 += qr[d + 3] * ks[j][d + 3];
            }
            float s = (s0 + s1) + (s2 + s3) + ms[j];
            if (s <= m) {
                float p = __expf(s - m);
                l += p;
#pragma unroll
                for (int d = 0; d < HD; d++) acc[d] += p * vs[j][d];
            } else {
                float c = __expf(m - s);
                m = s;
                l = l * c + 1.f;
#pragma unroll
                for (int d = 0; d < HD; d++) acc[d] = acc[d] * c + vs[j][d];
            }
        }
    }

    float inv = 1.f / l;
    float* orow = out + ((size_t)b * SEQ + r) * HID + qcol;
#pragma unroll
    for (int d = 0; d < HD; d++) orow[d] = acc[d] * inv;
}

// ---------------------------------------------------------------------------
extern "C" void kernel_launch(void* const* d_in, const int* in_sizes, int n_in,
                              void* d_out, int out_size) {
    const float* x    = (const float*)d_in[0];
    const float* mask = (const float*)d_in[1];
    const float* Wq   = (const float*)d_in[2];
    const float* bq   = (const float*)d_in[3];
    const float* Wk   = (const float*)d_in[4];
    const float* bk   = (const float*)d_in[5];
    const float* Wv   = (const float*)d_in[6];
    const float* bv   = (const float*)d_in[7];
    const float* Wo   = (const float*)d_in[8];
    const float* bo   = (const float*)d_in[9];
    float* out = (float*)d_out;

    float *q, *k, *v, *ao;
    cudaGetSymbolAddress((void**)&q,  g_q);
    cudaGetSymbolAddress((void**)&k,  g_k);
    cudaGetSymbolAddress((void**)&v,  g_v);
    cudaGetSymbolAddress((void**)&ao, g_ao);
    __nv_bfloat16 *xh, *xl, *aoh, *aol, *wqh, *wql, *wkh, *wkl, *wvh, *wvl, *woh, *wol;
    cudaGetSymbolAddress((void**)&xh,  g_xh);
    cudaGetSymbolAddress((void**)&xl,  g_xl);
    cudaGetSymbolAddress((void**)&aoh, g_aoh);
    cudaGetSymbolAddress((void**)&aol, g_aol);
    cudaGetSymbolAddress((void**)&wqh, g_wqh);
    cudaGetSymbolAddress((void**)&wql, g_wql);
    cudaGetSymbolAddress((void**)&wkh, g_wkh);
    cudaGetSymbolAddress((void**)&wkl, g_wkl);
    cudaGetSymbolAddress((void**)&wvh, g_wvh);
    cudaGetSymbolAddress((void**)&wvl, g_wvl);
    cudaGetSymbolAddress((void**)&woh, g_woh);
    cudaGetSymbolAddress((void**)&wol, g_wol);

    // 1) split inputs / weights to bf16 hi+lo
    {
        int n = MTOK * HID;
        split_hl<<<n / 1024, 256>>>(x, xh, xl, n);
    }
    split_transpose<<<dim3(HID / 32, HID / 32), 256>>>(Wq, wqh, wql, HID, HID);
    split_transpose<<<dim3(KVSZ / 32, HID / 32), 256>>>(Wk, wkh, wkl, HID, KVSZ);
    split_transpose<<<dim3(KVSZ / 32, HID / 32), 256>>>(Wv, wvh, wvl, HID, KVSZ);
    split_transpose<<<dim3(HID / 32, HID / 32), 256>>>(Wo, woh, wol, HID, HID);

    // 2) projections on tensor cores (HMMA)
    gemm_mma<<<dim3(HID / GBN,  MTOK / GBM), 256>>>(xh, xl, wqh, wql, bq, q, MTOK, HID,  HID);
    gemm_mma<<<dim3(KVSZ / GBN, MTOK / GBM), 256>>>(xh, xl, wkh, wkl, bk, k, MTOK, KVSZ, HID);
    gemm_mma<<<dim3(KVSZ / GBN, MTOK / GBM), 256>>>(xh, xl, wvh, wvl, bv, v, MTOK, KVSZ, HID);

    // 3) attention (fp32 SIMT, unchanged)
    flash_attn<<<dim3(SEQ / 128, HEADS, BATCH), 128>>>(q, k, v, mask, ao);

    // 4) output projection
    {
        int n = MTOK * HID;
        split_hl<<<n / 1024, 256>>>(ao, aoh, aol, n);
    }
    gemm_mma<<<dim3(HID / GBN, MTOK / GBM), 256>>>(aoh, aol, woh, wol, bo, out, MTOK, HID, HID);
}

// round 6
// speedup vs baseline: 1.0014x; 1.0014x over previous
#include <cuda_runtime.h>
#include <cuda_bf16.h>
#include <cstdint>
#include <cstddef>

// Problem constants
#define BATCH 2
#define SEQ 2048
#define HID 2048
#define KVSZ 512
#define HEADS 32
#define HD 64
#define MTOK (BATCH*SEQ)   // 4096 rows

// ---------------------------------------------------------------------------
// Scratch (device globals: allocation-free)
// ---------------------------------------------------------------------------
__device__ float g_q[(size_t)MTOK * HID];
__device__ float g_k[(size_t)MTOK * KVSZ];
__device__ float g_v[(size_t)MTOK * KVSZ];
__device__ float g_ao[(size_t)MTOK * HID];

__device__ __nv_bfloat16 g_xh[(size_t)MTOK * HID];
__device__ __nv_bfloat16 g_xl[(size_t)MTOK * HID];
__device__ __nv_bfloat16 g_aoh[(size_t)MTOK * HID];
__device__ __nv_bfloat16 g_aol[(size_t)MTOK * HID];
// transposed weights [N, K] bf16 hi/lo
__device__ __nv_bfloat16 g_wqh[(size_t)HID * HID];
__device__ __nv_bfloat16 g_wql[(size_t)HID * HID];
__device__ __nv_bfloat16 g_wkh[(size_t)KVSZ * HID];
__device__ __nv_bfloat16 g_wkl[(size_t)KVSZ * HID];
__device__ __nv_bfloat16 g_wvh[(size_t)KVSZ * HID];
__device__ __nv_bfloat16 g_wvl[(size_t)KVSZ * HID];
__device__ __nv_bfloat16 g_woh[(size_t)HID * HID];
__device__ __nv_bfloat16 g_wol[(size_t)HID * HID];

// ---------------------------------------------------------------------------
// Portable PTX helpers (no sm_103a-gated instructions!)
// ---------------------------------------------------------------------------
static __device__ __forceinline__ uint32_t smem_u32(const void* p) {
    uint32_t a;
    asm("{ .reg .u64 t; cvta.to.shared.u64 t, %1; cvt.u32.u64 %0, t; }" : "=r"(a) : "l"(p));
    return a;
}
static __device__ __forceinline__ void cp16(uint32_t dst, const void* src) {
    asm volatile("cp.async.cg.shared.global [%0], [%1], 16;" :: "r"(dst), "l"(src));
}
static __device__ __forceinline__ void ldsm4(uint32_t& r0, uint32_t& r1, uint32_t& r2,
                                             uint32_t& r3, uint32_t addr) {
    asm volatile("ldmatrix.sync.aligned.m8n8.x4.shared.b16 {%0,%1,%2,%3}, [%4];"
                 : "=r"(r0), "=r"(r1), "=r"(r2), "=r"(r3) : "r"(addr));
}
static __device__ __forceinline__ void mma16816(float* c, const uint32_t* a,
                                                const uint32_t* b) {
    asm volatile(
        "mma.sync.aligned.m16n8k16.row.col.f32.bf16.bf16.f32 "
        "{%0,%1,%2,%3}, {%4,%5,%6,%7}, {%8,%9}, {%0,%1,%2,%3};"
        : "+f"(c[0]), "+f"(c[1]), "+f"(c[2]), "+f"(c[3])
        : "r"(a[0]), "r"(a[1]), "r"(a[2]), "r"(a[3]), "r"(b[0]), "r"(b[1]));
}

// ---------------------------------------------------------------------------
// Split conversions: fp32 -> (hi, lo) bf16
// ---------------------------------------------------------------------------
__global__ void __launch_bounds__(256)
split_hl(const float* __restrict__ in, __nv_bfloat16* __restrict__ hi,
         __nv_bfloat16* __restrict__ lo, int n) {
    int i = (blockIdx.x * 256 + threadIdx.x) << 2;
    if (i >= n) return;
    float4 f = *(const float4*)(in + i);
    __nv_bfloat16 h0 = __float2bfloat16(f.x);
    __nv_bfloat16 h1 = __float2bfloat16(f.y);
    __nv_bfloat16 h2 = __float2bfloat16(f.z);
    __nv_bfloat16 h3 = __float2bfloat16(f.w);
    __nv_bfloat16 l0 = __float2bfloat16(f.x - __bfloat162float(h0));
    __nv_bfloat16 l1 = __float2bfloat16(f.y - __bfloat162float(h1));
    __nv_bfloat16 l2 = __float2bfloat16(f.z - __bfloat162float(h2));
    __nv_bfloat16 l3 = __float2bfloat16(f.w - __bfloat162float(h3));
    ushort4 uh = make_ushort4(__bfloat16_as_ushort(h0), __bfloat16_as_ushort(h1),
                              __bfloat16_as_ushort(h2), __bfloat16_as_ushort(h3));
    ushort4 ul = make_ushort4(__bfloat16_as_ushort(l0), __bfloat16_as_ushort(l1),
                              __bfloat16_as_ushort(l2), __bfloat16_as_ushort(l3));
    *(ushort4*)(hi + i) = uh;
    *(ushort4*)(lo + i) = ul;
}

// W [Kd, Nd] fp32 row-major -> th/tl [Nd, Kd] bf16 (transposed)
__global__ void __launch_bounds__(256)
split_transpose(const float* __restrict__ W, __nv_bfloat16* __restrict__ th,
                __nv_bfloat16* __restrict__ tl, int Kd, int Nd) {
    __shared__ float t[32][33];
    int n0 = blockIdx.x << 5, k0 = blockIdx.y << 5;
    int tx = threadIdx.x & 31, ty = threadIdx.x >> 5;  // ty 0..7
#pragma unroll
    for (int r = 0; r < 32; r += 8)
        t[ty + r][tx] = W[(size_t)(k0 + ty + r) * Nd + n0 + tx];
    __syncthreads();
#pragma unroll
    for (int r = 0; r < 32; r += 8) {
        float f = t[tx][ty + r];
        __nv_bfloat16 h = __float2bfloat16(f);
        __nv_bfloat16 l = __float2bfloat16(f - __bfloat162float(h));
        size_t o = (size_t)(n0 + ty + r) * Kd + k0 + tx;
        th[o] = h;
        tl[o] = l;
    }
}

// ---------------------------------------------------------------------------
// HMMA GEMM: C[M,N] = Ah@Bh^T + Ah@Bl^T + Al@Bh^T + bias  (fp32 out)
// A* [M,K] bf16 row-major; B* [N,K] bf16 row-major (W transposed).
// CTA tile 128x128, BK=32, 8 warps (each 64x32), cp.async double buffer.
// Smem rows padded to 80B (32 bf16 + 16B) -> conflict-free ldmatrix.
// ---------------------------------------------------------------------------
#define GBM 128
#define GBN 128
#define ROWB 80                         // bytes per smem row
#define TILEB (128 * ROWB)              // 10240 per matrix tile
#define STAGEB (2 * TILEB)              // A + B per stage

__global__ void __launch_bounds__(256)
gemm_mma(const __nv_bfloat16* __restrict__ Ah, const __nv_bfloat16* __restrict__ Al,
         const __nv_bfloat16* __restrict__ Bh, const __nv_bfloat16* __restrict__ Bl,
         const float* __restrict__ bias, float* __restrict__ C,
         int M, int N, int K)
{
    __shared__ __align__(16) char smem[2 * STAGEB];
    const uint32_t sb = smem_u32(smem);

    const int tid  = threadIdx.x;
    const int wid  = tid >> 5;
    const int lane = tid & 31;
    const int warp_m = (wid & 1) << 6;   // 0 / 64
    const int warp_n = (wid >> 1) << 5;  // 0 / 32 / 64 / 96

    const int row0 = blockIdx.y * GBM;
    const int col0 = blockIdx.x * GBN;

    const int KS = K >> 5;               // k-slabs per pass
    const int NS = 3 * KS;

    // cp.async mapping: 512 A-chunks + 512 B-chunks of 16B, 2 each per thread
    const int c_r  = tid >> 1;           // row 0..127
    const int c_c0 = (tid & 1) << 1;     // chunk 0 or 2

    // ldmatrix per-thread offsets
    const uint32_t a_off = (uint32_t)((warp_m + (lane & 7) + (((lane >> 3) & 1) << 3)) * ROWB
                                      + ((lane >> 4) << 4));            // +16B for k-half
    const uint32_t b_off = (uint32_t)((warp_n + (lane & 7) + ((lane >> 4) << 3)) * ROWB
                                      + (((lane >> 3) & 1) << 4));

    float acc[4][4][4];
#pragma unroll
    for (int i = 0; i < 4; i++)
#pragma unroll
        for (int j = 0; j < 4; j++)
#pragma unroll
            for (int t = 0; t < 4; t++) acc[i][j][t] = 0.f;

    // ---- stage loader ------------------------------------------------------
    auto load_stage = [&](int i, int s) {
        int p  = (i >= 2 * KS) ? 2 : ((i >= KS) ? 1 : 0);
        int kk = (i - p * KS) << 5;
        const __nv_bfloat16* Ag = ((p == 2) ? Al : Ah) + (size_t)row0 * K + kk;
        const __nv_bfloat16* Bg = ((p == 1) ? Bl : Bh) + (size_t)col0 * K + kk;
        uint32_t sa = sb + (uint32_t)s * STAGEB;
        uint32_t sbB = sa + TILEB;
        size_t rowbytes = (size_t)K * 2;
        const char* agc = (const char*)Ag + (size_t)c_r * rowbytes;
        const char* bgc = (const char*)Bg + (size_t)c_r * rowbytes;
        uint32_t so = (uint32_t)(c_r * ROWB + c_c0 * 16);
        cp16(sa  + so,      agc + c_c0 * 16);
        cp16(sa  + so + 16, agc + c_c0 * 16 + 16);
        cp16(sbB + so,      bgc + c_c0 * 16);
        cp16(sbB + so + 16, bgc + c_c0 * 16 + 16);
        asm volatile("cp.async.commit_group;" ::: "memory");
    };

    load_stage(0, 0);

    for (int i = 0; i < NS; i++) {
        int s = i & 1;
        if (i + 1 < NS) {
            load_stage(i + 1, s ^ 1);
            asm volatile("cp.async.wait_group 1;" ::: "memory");
        } else {
            asm volatile("cp.async.wait_group 0;" ::: "memory");
        }
        __syncthreads();

        uint32_t sa  = sb + (uint32_t)s * STAGEB;
        uint32_t sbB = sa + TILEB;
#pragma unroll
        for (int ks = 0; ks < 2; ks++) {          // two k16 steps per BK=32
            uint32_t kb = (uint32_t)(ks << 5);    // 16 halves = 32 bytes
            uint32_t a[4][4], b[4][2];
#pragma unroll
            for (int mt = 0; mt < 4; mt++)
                ldsm4(a[mt][0], a[mt][1], a[mt][2], a[mt][3],
                      sa + a_off + (uint32_t)(mt << 4) * ROWB + kb);
#pragma unroll
            for (int np = 0; np < 2; np++)
                ldsm4(b[2*np][0], b[2*np][1], b[2*np+1][0], b[2*np+1][1],
                      sbB + b_off + (uint32_t)(np << 4) * ROWB + kb);
#pragma unroll
            for (int mt = 0; mt < 4; mt++)
#pragma unroll
                for (int nt = 0; nt < 4; nt++)
                    mma16816(acc[mt][nt], a[mt], b[nt]);
        }
        __syncthreads();
    }

    // ---- epilogue -----------------------------------------------------------
    const int qr = lane >> 2;            // quad row 0..7
    const int qc = (lane & 3) << 1;      // col pair 0,2,4,6
#pragma unroll
    for (int mt = 0; mt < 4; mt++) {
        int r = row0 + warp_m + (mt << 4) + qr;
        float* C0 = C + (size_t)r * N;
        float* C1 = C + (size_t)(r + 8) * N;
#pragma unroll
        for (int nt = 0; nt < 4; nt++) {
            int c = col0 + warp_n + (nt << 3) + qc;
            float b0 = bias[c], b1 = bias[c + 1];
            float2 v0 = make_float2(acc[mt][nt][0] + b0, acc[mt][nt][1] + b1);
            float2 v1 = make_float2(acc[mt][nt][2] + b0, acc[mt][nt][3] + b1);
            *(float2*)(C0 + c) = v0;
            *(float2*)(C1 + c) = v1;
        }
    }
}

// ---------------------------------------------------------------------------
// Flash attention, fp32 (unchanged — passing at rel_err 1.9e-6)
// ---------------------------------------------------------------------------
__global__ __launch_bounds__(128, 2)
void flash_attn(const float* __restrict__ q, const float* __restrict__ k,
                const float* __restrict__ v, const float* __restrict__ mask,
                float* __restrict__ out) {
    const int BN = 64;
    int h = blockIdx.y;
    int b = blockIdx.z;
    int r = blockIdx.x * 128 + threadIdx.x;
    int qcol = h * HD;
    int kcol = (h >> 2) * HD;

    const float scale = 0.125f;
    float qr[HD];
    {
        const float* qrow = q + ((size_t)b * SEQ + r) * HID + qcol;
#pragma unroll
        for (int d = 0; d < HD; d++) qr[d] = qrow[d] * scale;
    }

    float m = -1e30f, l = 0.f;
    float acc[HD];
#pragma unroll
    for (int d = 0; d < HD; d++) acc[d] = 0.f;

    __shared__ float ks[BN][HD];
    __shared__ float vs[BN][HD];
    __shared__ float ms[BN];

    const float* kbase = k + (size_t)b * SEQ * KVSZ + kcol;
    const float* vbase = v + (size_t)b * SEQ * KVSZ + kcol;
    const float* mbase = mask + (size_t)b * SEQ;

    for (int kt = 0; kt < SEQ; kt += BN) {
        __syncthreads();
        for (int i = threadIdx.x; i < BN * (HD / 4); i += 128) {
            int j  = i >> 4;
            int d4 = (i & 15) << 2;
            *(float4*)&ks[j][d4] = *(const float4*)&kbase[(size_t)(kt + j) * KVSZ + d4];
            *(float4*)&vs[j][d4] = *(const float4*)&vbase[(size_t)(kt + j) * KVSZ + d4];
        }
        if (threadIdx.x < BN) ms[threadIdx.x] = mbase[kt + threadIdx.x];
        __syncthreads();

        for (int j = 0; j < BN; j++) {
            float s0 = 0.f, s1 = 0.f, s2 = 0.f, s3 = 0.f;
#pragma unroll
            for (int d = 0; d < HD; d += 4) {
                s0 += qr[d + 0] * ks[j][d + 0];
                s1 += qr[d + 1] * ks[j][d + 1];
                s2 += qr[d + 2] * ks[j][d + 2];
                s3 += qr[d + 3] * ks[j][d + 3];
            }
            float s = (s0 + s1) + (s2 + s3) + ms[j];
            if (s <= m) {
                float p = __expf(s - m);
                l += p;
#pragma unroll
                for (int d = 0; d < HD; d++) acc[d] += p * vs[j][d];
            } else {
                float c = __expf(m - s);
                m = s;
                l = l * c + 1.f;
#pragma unroll
                for (int d = 0; d < HD; d++) acc[d] = acc[d] * c + vs[j][d];
            }
        }
    }

    float inv = 1.f / l;
    float* orow = out + ((size_t)b * SEQ + r) * HID + qcol;
#pragma unroll
    for (int d = 0; d < HD; d++) orow[d] = acc[d] * inv;
}

// ---------------------------------------------------------------------------
extern "C" void kernel_launch(void* const* d_in, const int* in_sizes, int n_in,
                              void* d_out, int out_size) {
    const float* x    = (const float*)d_in[0];
    const float* mask = (const float*)d_in[1];
    const float* Wq   = (const float*)d_in[2];
    const float* bq   = (const float*)d_in[3];
    const float* Wk   = (const float*)d_in[4];
    const float* bk   = (const float*)d_in[5];
    const float* Wv   = (const float*)d_in[6];
    const float* bv   = (const float*)d_in[7];
    const float* Wo   = (const float*)d_in[8];
    const float* bo   = (const float*)d_in[9];
    float* out = (float*)d_out;

    float *q, *k, *v, *ao;
    cudaGetSymbolAddress((void**)&q,  g_q);
    cudaGetSymbolAddress((void**)&k,  g_k);
    cudaGetSymbolAddress((void**)&v,  g_v);
    cudaGetSymbolAddress((void**)&ao, g_ao);
    __nv_bfloat16 *xh, *xl, *aoh, *aol, *wqh, *wql, *wkh, *wkl, *wvh, *wvl, *woh, *wol;
    cudaGetSymbolAddress((void**)&xh,  g_xh);
    cudaGetSymbolAddress((void**)&xl,  g_xl);
    cudaGetSymbolAddress((void**)&aoh, g_aoh);
    cudaGetSymbolAddress((void**)&aol, g_aol);
    cudaGetSymbolAddress((void**)&wqh, g_wqh);
    cudaGetSymbolAddress((void**)&wql, g_wql);
    cudaGetSymbolAddress((void**)&wkh, g_wkh);
    cudaGetSymbolAddress((void**)&wkl, g_wkl);
    cudaGetSymbolAddress((void**)&wvh, g_wvh);
    cudaGetSymbolAddress((void**)&wvl, g_wvl);
    cudaGetSymbolAddress((void**)&woh, g_woh);
    cudaGetSymbolAddress((void**)&wol, g_wol);

    // 1) split inputs / weights to bf16 hi+lo
    {
        int n = MTOK * HID;
        split_hl<<<n / 1024, 256>>>(x, xh, xl, n);
    }
    split_transpose<<<dim3(HID / 32, HID / 32), 256>>>(Wq, wqh, wql, HID, HID);
    split_transpose<<<dim3(KVSZ / 32, HID / 32), 256>>>(Wk, wkh, wkl, HID, KVSZ);
    split_transpose<<<dim3(KVSZ / 32, HID / 32), 256>>>(Wv, wvh, wvl, HID, KVSZ);
    split_transpose<<<dim3(HID / 32, HID / 32), 256>>>(Wo, woh, wol, HID, HID);

    // 2) projections on tensor cores (HMMA)
    gemm_mma<<<dim3(HID / GBN,  MTOK / GBM), 256>>>(xh, xl, wqh, wql, bq, q, MTOK, HID,  HID);
    gemm_mma<<<dim3(KVSZ / GBN, MTOK / GBM), 256>>>(xh, xl, wkh, wkl, bk, k, MTOK, KVSZ, HID);
    gemm_mma<<<dim3(KVSZ / GBN, MTOK / GBM), 256>>>(xh, xl, wvh, wvl, bv, v, MTOK, KVSZ, HID);

    // 3) attention (fp32 SIMT, unchanged)
    flash_attn<<<dim3(SEQ / 128, HEADS, BATCH), 128>>>(q, k, v, mask, ao);

    // 4) output projection
    {
        int n = MTOK * HID;
        split_hl<<<n / 1024, 256>>>(ao, aoh, aol, n);
    }
    gemm_mma<<<dim3(HID / GBN, MTOK / GBM), 256>>>(aoh, aol, woh, wol, bo, out, MTOK, HID, HID);
}

// round 7
// speedup vs baseline: 2.2435x; 2.2404x over previous
#include <cuda_runtime.h>
#include <cuda_bf16.h>
#include <cstdint>
#include <cstddef>

// Problem constants
#define BATCH 2
#define SEQ 2048
#define HID 2048
#define KVSZ 512
#define HEADS 32
#define HD 64
#define MTOK (BATCH*SEQ)   // 4096 rows
#define LOG2E 1.4426950408889634f

// ---------------------------------------------------------------------------
// Scratch (device globals: allocation-free)
// ---------------------------------------------------------------------------
__device__ __nv_bfloat16 g_xh[(size_t)MTOK * HID];
__device__ __nv_bfloat16 g_xl[(size_t)MTOK * HID];
__device__ __nv_bfloat16 g_qh[(size_t)MTOK * HID];
__device__ __nv_bfloat16 g_ql[(size_t)MTOK * HID];
__device__ __nv_bfloat16 g_kh[(size_t)MTOK * KVSZ];
__device__ __nv_bfloat16 g_kl[(size_t)MTOK * KVSZ];
__device__ __nv_bfloat16 g_vh[(size_t)MTOK * KVSZ];
__device__ __nv_bfloat16 g_vl[(size_t)MTOK * KVSZ];
__device__ __nv_bfloat16 g_aoh[(size_t)MTOK * HID];
__device__ __nv_bfloat16 g_aol[(size_t)MTOK * HID];
// transposed weights [N, K] bf16 hi/lo
__device__ __nv_bfloat16 g_wqh[(size_t)HID * HID];
__device__ __nv_bfloat16 g_wql[(size_t)HID * HID];
__device__ __nv_bfloat16 g_wkh[(size_t)KVSZ * HID];
__device__ __nv_bfloat16 g_wkl[(size_t)KVSZ * HID];
__device__ __nv_bfloat16 g_wvh[(size_t)KVSZ * HID];
__device__ __nv_bfloat16 g_wvl[(size_t)KVSZ * HID];
__device__ __nv_bfloat16 g_woh[(size_t)HID * HID];
__device__ __nv_bfloat16 g_wol[(size_t)HID * HID];

// ---------------------------------------------------------------------------
// Portable PTX helpers (no sm_103a-gated instructions)
// ---------------------------------------------------------------------------
static __device__ __forceinline__ uint32_t smem_u32(const void* p) {
    uint32_t a;
    asm("{ .reg .u64 t; cvta.to.shared.u64 t, %1; cvt.u32.u64 %0, t; }" : "=r"(a) : "l"(p));
    return a;
}
static __device__ __forceinline__ void cp16(uint32_t dst, const void* src) {
    asm volatile("cp.async.cg.shared.global [%0], [%1], 16;" :: "r"(dst), "l"(src));
}
static __device__ __forceinline__ void ldsm4(uint32_t& r0, uint32_t& r1, uint32_t& r2,
                                             uint32_t& r3, uint32_t addr) {
    asm volatile("ldmatrix.sync.aligned.m8n8.x4.shared.b16 {%0,%1,%2,%3}, [%4];"
                 : "=r"(r0), "=r"(r1), "=r"(r2), "=r"(r3) : "r"(addr));
}
static __device__ __forceinline__ void ldsm4t(uint32_t& r0, uint32_t& r1, uint32_t& r2,
                                              uint32_t& r3, uint32_t addr) {
    asm volatile("ldmatrix.sync.aligned.m8n8.x4.trans.shared.b16 {%0,%1,%2,%3}, [%4];"
                 : "=r"(r0), "=r"(r1), "=r"(r2), "=r"(r3) : "r"(addr));
}
static __device__ __forceinline__ void mma16816(float* c, const uint32_t* a,
                                                const uint32_t* b) {
    asm volatile(
        "mma.sync.aligned.m16n8k16.row.col.f32.bf16.bf16.f32 "
        "{%0,%1,%2,%3}, {%4,%5,%6,%7}, {%8,%9}, {%0,%1,%2,%3};"
        : "+f"(c[0]), "+f"(c[1]), "+f"(c[2]), "+f"(c[3])
        : "r"(a[0]), "r"(a[1]), "r"(a[2]), "r"(a[3]), "r"(b[0]), "r"(b[1]));
}
// fp32 pair -> packed bf16x2 hi + packed bf16x2 lo (residual)
static __device__ __forceinline__ void split_pack(float x, float y,
                                                  uint32_t& h, uint32_t& l) {
    __nv_bfloat16 hx = __float2bfloat16(x), hy = __float2bfloat16(y);
    float rx = x - __bfloat162float(hx);
    float ry = y - __bfloat162float(hy);
    __nv_bfloat16 lx = __float2bfloat16(rx), ly = __float2bfloat16(ry);
    h = (uint32_t)__bfloat16_as_ushort(hx) | ((uint32_t)__bfloat16_as_ushort(hy) << 16);
    l = (uint32_t)__bfloat16_as_ushort(lx) | ((uint32_t)__bfloat16_as_ushort(ly) << 16);
}

// ---------------------------------------------------------------------------
// fp32 -> (hi, lo) bf16 elementwise
// ---------------------------------------------------------------------------
__global__ void __launch_bounds__(256)
split_hl(const float* __restrict__ in, __nv_bfloat16* __restrict__ hi,
         __nv_bfloat16* __restrict__ lo, int n) {
    int i = (blockIdx.x * 256 + threadIdx.x) << 2;
    if (i >= n) return;
    float4 f = *(const float4*)(in + i);
    uint32_t h01, l01, h23, l23;
    split_pack(f.x, f.y, h01, l01);
    split_pack(f.z, f.w, h23, l23);
    *(uint2*)(hi + i) = make_uint2(h01, h23);
    *(uint2*)(lo + i) = make_uint2(l01, l23);
}

// W [Kd, Nd] fp32 row-major -> th/tl [Nd, Kd] bf16 (transposed)
__global__ void __launch_bounds__(256)
split_transpose(const float* __restrict__ W, __nv_bfloat16* __restrict__ th,
                __nv_bfloat16* __restrict__ tl, int Kd, int Nd) {
    __shared__ float t[32][33];
    int n0 = blockIdx.x << 5, k0 = blockIdx.y << 5;
    int tx = threadIdx.x & 31, ty = threadIdx.x >> 5;
#pragma unroll
    for (int r = 0; r < 32; r += 8)
        t[ty + r][tx] = W[(size_t)(k0 + ty + r) * Nd + n0 + tx];
    __syncthreads();
#pragma unroll
    for (int r = 0; r < 32; r += 8) {
        float f = t[tx][ty + r];
        __nv_bfloat16 h = __float2bfloat16(f);
        __nv_bfloat16 l = __float2bfloat16(f - __bfloat162float(h));
        size_t o = (size_t)(n0 + ty + r) * Kd + k0 + tx;
        th[o] = h;
        tl[o] = l;
    }
}

// ---------------------------------------------------------------------------
// HMMA GEMM: C = Ah@Bh^T + Ah@Bl^T + Al@Bh^T + bias
// Output either fp32 (Cf) or bf16 hi/lo split of (acc+bias)*scale (Ch/Cl).
// ---------------------------------------------------------------------------
#define GBM 128
#define GBN 128
#define ROWB 80
#define TILEB (128 * ROWB)
#define STAGEB (2 * TILEB)

__global__ void __launch_bounds__(256)
gemm_mma(const __nv_bfloat16* __restrict__ Ah, const __nv_bfloat16* __restrict__ Al,
         const __nv_bfloat16* __restrict__ Bh, const __nv_bfloat16* __restrict__ Bl,
         const float* __restrict__ bias,
         float* __restrict__ Cf,
         __nv_bfloat16* __restrict__ Ch, __nv_bfloat16* __restrict__ Cl,
         float scale, int M, int N, int K)
{
    __shared__ __align__(16) char smem[2 * STAGEB];
    const uint32_t sb = smem_u32(smem);

    const int tid  = threadIdx.x;
    const int wid  = tid >> 5;
    const int lane = tid & 31;
    const int warp_m = (wid & 1) << 6;
    const int warp_n = (wid >> 1) << 5;

    const int row0 = blockIdx.y * GBM;
    const int col0 = blockIdx.x * GBN;

    const int KS = K >> 5;
    const int NS = 3 * KS;

    const int c_r  = tid >> 1;
    const int c_c0 = (tid & 1) << 1;

    const uint32_t a_off = (uint32_t)((warp_m + (lane & 7) + (((lane >> 3) & 1) << 3)) * ROWB
                                      + ((lane >> 4) << 4));
    const uint32_t b_off = (uint32_t)((warp_n + (lane & 7) + ((lane >> 4) << 3)) * ROWB
                                      + (((lane >> 3) & 1) << 4));

    float acc[4][4][4];
#pragma unroll
    for (int i = 0; i < 4; i++)
#pragma unroll
        for (int j = 0; j < 4; j++)
#pragma unroll
            for (int t = 0; t < 4; t++) acc[i][j][t] = 0.f;

    auto load_stage = [&](int i, int s) {
        int p  = (i >= 2 * KS) ? 2 : ((i >= KS) ? 1 : 0);
        int kk = (i - p * KS) << 5;
        const __nv_bfloat16* Ag = ((p == 2) ? Al : Ah) + (size_t)row0 * K + kk;
        const __nv_bfloat16* Bg = ((p == 1) ? Bl : Bh) + (size_t)col0 * K + kk;
        uint32_t sa = sb + (uint32_t)s * STAGEB;
        uint32_t sbB = sa + TILEB;
        size_t rowbytes = (size_t)K * 2;
        const char* agc = (const char*)Ag + (size_t)c_r * rowbytes;
        const char* bgc = (const char*)Bg + (size_t)c_r * rowbytes;
        uint32_t so = (uint32_t)(c_r * ROWB + c_c0 * 16);
        cp16(sa  + so,      agc + c_c0 * 16);
        cp16(sa  + so + 16, agc + c_c0 * 16 + 16);
        cp16(sbB + so,      bgc + c_c0 * 16);
        cp16(sbB + so + 16, bgc + c_c0 * 16 + 16);
        asm volatile("cp.async.commit_group;" ::: "memory");
    };

    load_stage(0, 0);

    for (int i = 0; i < NS; i++) {
        int s = i & 1;
        if (i + 1 < NS) {
            load_stage(i + 1, s ^ 1);
            asm volatile("cp.async.wait_group 1;" ::: "memory");
        } else {
            asm volatile("cp.async.wait_group 0;" ::: "memory");
        }
        __syncthreads();

        uint32_t sa  = sb + (uint32_t)s * STAGEB;
        uint32_t sbB = sa + TILEB;
#pragma unroll
        for (int ks = 0; ks < 2; ks++) {
            uint32_t kb = (uint32_t)(ks << 5);
            uint32_t a[4][4], b[4][2];
#pragma unroll
            for (int mt = 0; mt < 4; mt++)
                ldsm4(a[mt][0], a[mt][1], a[mt][2], a[mt][3],
                      sa + a_off + (uint32_t)(mt << 4) * ROWB + kb);
#pragma unroll
            for (int np = 0; np < 2; np++)
                ldsm4(b[2*np][0], b[2*np][1], b[2*np+1][0], b[2*np+1][1],
                      sbB + b_off + (uint32_t)(np << 4) * ROWB + kb);
#pragma unroll
            for (int mt = 0; mt < 4; mt++)
#pragma unroll
                for (int nt = 0; nt < 4; nt++)
                    mma16816(acc[mt][nt], a[mt], b[nt]);
        }
        __syncthreads();
    }

    const int qr = lane >> 2;
    const int qc = (lane & 3) << 1;
    if (Cf) {
#pragma unroll
        for (int mt = 0; mt < 4; mt++) {
            int r = row0 + warp_m + (mt << 4) + qr;
            float* C0 = Cf + (size_t)r * N;
            float* C1 = Cf + (size_t)(r + 8) * N;
#pragma unroll
            for (int nt = 0; nt < 4; nt++) {
                int c = col0 + warp_n + (nt << 3) + qc;
                float b0 = bias[c], b1 = bias[c + 1];
                *(float2*)(C0 + c) = make_float2(acc[mt][nt][0] + b0, acc[mt][nt][1] + b1);
                *(float2*)(C1 + c) = make_float2(acc[mt][nt][2] + b0, acc[mt][nt][3] + b1);
            }
        }
    } else {
#pragma unroll
        for (int mt = 0; mt < 4; mt++) {
            int r = row0 + warp_m + (mt << 4) + qr;
#pragma unroll
            for (int nt = 0; nt < 4; nt++) {
                int c = col0 + warp_n + (nt << 3) + qc;
                float b0 = bias[c], b1 = bias[c + 1];
                uint32_t h01, l01, h23, l23;
                split_pack((acc[mt][nt][0] + b0) * scale, (acc[mt][nt][1] + b1) * scale, h01, l01);
                split_pack((acc[mt][nt][2] + b0) * scale, (acc[mt][nt][3] + b1) * scale, h23, l23);
                *(uint32_t*)(Ch + (size_t)r * N + c)       = h01;
                *(uint32_t*)(Cl + (size_t)r * N + c)       = l01;
                *(uint32_t*)(Ch + (size_t)(r + 8) * N + c) = h23;
                *(uint32_t*)(Cl + (size_t)(r + 8) * N + c) = l23;
            }
        }
    }
}

// ---------------------------------------------------------------------------
// HMMA flash attention, hi/lo compensated bf16.
// 4 warps, 64 q-rows/block, 64 kv-cols/iter, cp.async double buffer.
// grid = (SEQ/64, HEADS, BATCH), block = 128.
// ---------------------------------------------------------------------------
#define FROWB 144                       // 64 bf16 + 16B pad (conflict-free ldmatrix)
#define FTILEB (64 * FROWB)             // 9216
#define FSTAGEB (4 * FTILEB + 256)      // Kh,Kl,Vh,Vl + mask tile
#define FSMEM (2 * FSTAGEB)             // 74240

__global__ void __launch_bounds__(128)
flash_mma(const __nv_bfloat16* __restrict__ qh, const __nv_bfloat16* __restrict__ ql,
          const __nv_bfloat16* __restrict__ kh, const __nv_bfloat16* __restrict__ kl,
          const __nv_bfloat16* __restrict__ vh, const __nv_bfloat16* __restrict__ vl,
          const float* __restrict__ mask,
          __nv_bfloat16* __restrict__ oh, __nv_bfloat16* __restrict__ ol)
{
    extern __shared__ char fsm[];
    const uint32_t sb = smem_u32(fsm);
    const int tid  = threadIdx.x;
    const int wid  = tid >> 5;
    const int lane = tid & 31;
    const int h  = blockIdx.y;
    const int bb = blockIdx.z;
    const int row0 = blockIdx.x * 64;
    const int fr = lane >> 2;            // 0..7
    const int fc = (lane & 3) << 1;      // 0,2,4,6

    // --- Q fragments direct from gmem (scale pre-folded in projection) ------
    uint32_t qhf[4][4], qlf[4][4];
    {
        const size_t rowbase = (size_t)(bb * SEQ + row0 + wid * 16);
#pragma unroll
        for (int ki = 0; ki < 4; ki++)
#pragma unroll
            for (int part = 0; part < 4; part++) {
                int r = fr + ((part & 1) << 3);
                int c = (ki << 4) + fc + ((part >> 1) << 3);
                size_t off = (rowbase + r) * HID + h * HD + c;
                qhf[ki][part] = *(const uint32_t*)(qh + off);
                qlf[ki][part] = *(const uint32_t*)(ql + off);
            }
    }

    const int kvcol = (h >> 2) * HD;

    auto load_stage = [&](int kt, int s) {
        uint32_t base = sb + (uint32_t)s * FSTAGEB;
        size_t rb = ((size_t)bb * SEQ + kt) * KVSZ + kvcol;
        const char* src[4] = { (const char*)(kh + rb), (const char*)(kl + rb),
                               (const char*)(vh + rb), (const char*)(vl + rb) };
        for (int i = tid; i < 2064; i += 128) {
            if (i < 2048) {
                int t = i >> 9, idx = i & 511, r = idx >> 3, c = idx & 7;
                cp16(base + (uint32_t)(t * FTILEB + r * FROWB + (c << 4)),
                     src[t] + ((size_t)r * KVSZ) * 2 + (c << 4));
            } else {
                int j = i - 2048;
                cp16(base + (uint32_t)(4 * FTILEB + (j << 4)),
                     (const char*)(mask + (size_t)bb * SEQ + kt) + (j << 4));
            }
        }
        asm volatile("cp.async.commit_group;" ::: "memory");
    };

    float o[8][4];
#pragma unroll
    for (int i = 0; i < 8; i++)
#pragma unroll
        for (int j = 0; j < 4; j++) o[i][j] = 0.f;
    float m0 = -1e30f, m1 = -1e30f, l0 = 0.f, l1 = 0.f;

    load_stage(0, 0);

    for (int kt = 0; kt < SEQ; kt += 64) {
        int s = (kt >> 6) & 1;
        if (kt + 64 < SEQ) {
            load_stage(kt + 64, s ^ 1);
            asm volatile("cp.async.wait_group 1;" ::: "memory");
        } else {
            asm volatile("cp.async.wait_group 0;" ::: "memory");
        }
        __syncthreads();

        const uint32_t kbh = sb + (uint32_t)s * FSTAGEB;
        const uint32_t kbl = kbh + FTILEB;
        const uint32_t vbh = kbh + 2 * FTILEB;
        const uint32_t vbl = kbh + 3 * FTILEB;
        const float* msk = (const float*)(fsm + (size_t)s * FSTAGEB + 4 * FTILEB);

        // ---- S = Qh@Kh + Ql@Kh + Qh@Kl --------------------------------------
        float sc[8][4];
#pragma unroll
        for (int i = 0; i < 8; i++)
#pragma unroll
            for (int j = 0; j < 4; j++) sc[i][j] = 0.f;

#pragma unroll
        for (int ki = 0; ki < 4; ki++) {
            uint32_t koff = (uint32_t)(((lane & 7) + ((lane >> 4) << 3)) * FROWB
                            + (((lane >> 3) & 1) << 4) + (ki << 5));
#pragma unroll
            for (int np = 0; np < 4; np++) {
                uint32_t bh[4], bl2[4];
                ldsm4(bh[0], bh[1], bh[2], bh[3],
                      kbh + (uint32_t)(np * 16 * FROWB) + koff);
                ldsm4(bl2[0], bl2[1], bl2[2], bl2[3],
                      kbl + (uint32_t)(np * 16 * FROWB) + koff);
                mma16816(sc[2*np],   qhf[ki], bh);
                mma16816(sc[2*np+1], qhf[ki], bh + 2);
                mma16816(sc[2*np],   qlf[ki], bh);
                mma16816(sc[2*np+1], qlf[ki], bh + 2);
                mma16816(sc[2*np],   qhf[ki], bl2);
                mma16816(sc[2*np+1], qhf[ki], bl2 + 2);
            }
        }

        // ---- mask + online softmax (exp2 domain) ---------------------------
        float mx0 = -1e30f, mx1 = -1e30f;
#pragma unroll
        for (int ni = 0; ni < 8; ni++) {
            float mk0 = msk[ni * 8 + fc] * LOG2E;
            float mk1 = msk[ni * 8 + fc + 1] * LOG2E;
            sc[ni][0] += mk0; sc[ni][1] += mk1;
            sc[ni][2] += mk0; sc[ni][3] += mk1;
            mx0 = fmaxf(mx0, fmaxf(sc[ni][0], sc[ni][1]));
            mx1 = fmaxf(mx1, fmaxf(sc[ni][2], sc[ni][3]));
        }
        mx0 = fmaxf(mx0, __shfl_xor_sync(0xFFFFFFFFu, mx0, 1));
        mx0 = fmaxf(mx0, __shfl_xor_sync(0xFFFFFFFFu, mx0, 2));
        mx1 = fmaxf(mx1, __shfl_xor_sync(0xFFFFFFFFu, mx1, 1));
        mx1 = fmaxf(mx1, __shfl_xor_sync(0xFFFFFFFFu, mx1, 2));
        float mn0 = fmaxf(m0, mx0), mn1 = fmaxf(m1, mx1);
        float c0 = exp2f(m0 - mn0), c1 = exp2f(m1 - mn1);
        m0 = mn0; m1 = mn1;
        l0 *= c0;  l1 *= c1;
#pragma unroll
        for (int ni = 0; ni < 8; ni++) {
            o[ni][0] *= c0; o[ni][1] *= c0; o[ni][2] *= c1; o[ni][3] *= c1;
            sc[ni][0] = exp2f(sc[ni][0] - m0);
            sc[ni][1] = exp2f(sc[ni][1] - m0);
            sc[ni][2] = exp2f(sc[ni][2] - m1);
            sc[ni][3] = exp2f(sc[ni][3] - m1);
            l0 += sc[ni][0] + sc[ni][1];
            l1 += sc[ni][2] + sc[ni][3];
        }

        // ---- O += Ph@Vh + Pl@Vh + Ph@Vl -------------------------------------
#pragma unroll
        for (int ki = 0; ki < 4; ki++) {
            uint32_t ph[4], pl[4];
            split_pack(sc[2*ki][0],   sc[2*ki][1],   ph[0], pl[0]);
            split_pack(sc[2*ki][2],   sc[2*ki][3],   ph[1], pl[1]);
            split_pack(sc[2*ki+1][0], sc[2*ki+1][1], ph[2], pl[2]);
            split_pack(sc[2*ki+1][2], sc[2*ki+1][3], ph[3], pl[3]);
            uint32_t voff = (uint32_t)((ki * 16 + (lane & 7) + (((lane >> 3) & 1) << 3)) * FROWB
                            + ((lane >> 4) << 4));
#pragma unroll
            for (int np = 0; np < 4; np++) {
                uint32_t bh[4], bl2[4];
                ldsm4t(bh[0], bh[1], bh[2], bh[3], vbh + voff + (uint32_t)(np << 5));
                ldsm4t(bl2[0], bl2[1], bl2[2], bl2[3], vbl + voff + (uint32_t)(np << 5));
                mma16816(o[2*np],   ph, bh);
                mma16816(o[2*np+1], ph, bh + 2);
                mma16816(o[2*np],   pl, bh);
                mma16816(o[2*np+1], pl, bh + 2);
                mma16816(o[2*np],   ph, bl2);
                mma16816(o[2*np+1], ph, bl2 + 2);
            }
        }
        __syncthreads();
    }

    // ---- finalize: row-sum reduce, normalize, split-store -------------------
    l0 += __shfl_xor_sync(0xFFFFFFFFu, l0, 1);
    l0 += __shfl_xor_sync(0xFFFFFFFFu, l0, 2);
    l1 += __shfl_xor_sync(0xFFFFFFFFu, l1, 1);
    l1 += __shfl_xor_sync(0xFFFFFFFFu, l1, 2);
    float i0 = 1.f / l0, i1 = 1.f / l1;

    const size_t rb = (size_t)(bb * SEQ + row0 + wid * 16);
#pragma unroll
    for (int ni = 0; ni < 8; ni++) {
        int c = h * HD + ni * 8 + fc;
        uint32_t h01, l01, h23, l23;
        split_pack(o[ni][0] * i0, o[ni][1] * i0, h01, l01);
        split_pack(o[ni][2] * i1, o[ni][3] * i1, h23, l23);
        *(uint32_t*)(oh + (rb + fr) * HID + c)     = h01;
        *(uint32_t*)(ol + (rb + fr) * HID + c)     = l01;
        *(uint32_t*)(oh + (rb + fr + 8) * HID + c) = h23;
        *(uint32_t*)(ol + (rb + fr + 8) * HID + c) = l23;
    }
}

// ---------------------------------------------------------------------------
extern "C" void kernel_launch(void* const* d_in, const int* in_sizes, int n_in,
                              void* d_out, int out_size) {
    const float* x    = (const float*)d_in[0];
    const float* mask = (const float*)d_in[1];
    const float* Wq   = (const float*)d_in[2];
    const float* bq   = (const float*)d_in[3];
    const float* Wk   = (const float*)d_in[4];
    const float* bk   = (const float*)d_in[5];
    const float* Wv   = (const float*)d_in[6];
    const float* bv   = (const float*)d_in[7];
    const float* Wo   = (const float*)d_in[8];
    const float* bo   = (const float*)d_in[9];
    float* out = (float*)d_out;

    __nv_bfloat16 *xh, *xl, *qh, *ql, *kh, *kl, *vh, *vl, *aoh, *aol;
    __nv_bfloat16 *wqh, *wql, *wkh, *wkl, *wvh, *wvl, *woh, *wol;
    cudaGetSymbolAddress((void**)&xh,  g_xh);
    cudaGetSymbolAddress((void**)&xl,  g_xl);
    cudaGetSymbolAddress((void**)&qh,  g_qh);
    cudaGetSymbolAddress((void**)&ql,  g_ql);
    cudaGetSymbolAddress((void**)&kh,  g_kh);
    cudaGetSymbolAddress((void**)&kl,  g_kl);
    cudaGetSymbolAddress((void**)&vh,  g_vh);
    cudaGetSymbolAddress((void**)&vl,  g_vl);
    cudaGetSymbolAddress((void**)&aoh, g_aoh);
    cudaGetSymbolAddress((void**)&aol, g_aol);
    cudaGetSymbolAddress((void**)&wqh, g_wqh);
    cudaGetSymbolAddress((void**)&wql, g_wql);
    cudaGetSymbolAddress((void**)&wkh, g_wkh);
    cudaGetSymbolAddress((void**)&wkl, g_wkl);
    cudaGetSymbolAddress((void**)&wvh, g_wvh);
    cudaGetSymbolAddress((void**)&wvl, g_wvl);
    cudaGetSymbolAddress((void**)&woh, g_woh);
    cudaGetSymbolAddress((void**)&wol, g_wol);

    cudaFuncSetAttribute(flash_mma, cudaFuncAttributeMaxDynamicSharedMemorySize, FSMEM);

    // 1) split x and weights to bf16 hi+lo
    {
        int n = MTOK * HID;
        split_hl<<<n / 1024, 256>>>(x, xh, xl, n);
    }
    split_transpose<<<dim3(HID / 32, HID / 32), 256>>>(Wq, wqh, wql, HID, HID);
    split_transpose<<<dim3(KVSZ / 32, HID / 32), 256>>>(Wk, wkh, wkl, HID, KVSZ);
    split_transpose<<<dim3(KVSZ / 32, HID / 32), 256>>>(Wv, wvh, wvl, HID, KVSZ);
    split_transpose<<<dim3(HID / 32, HID / 32), 256>>>(Wo, woh, wol, HID, HID);

    // 2) projections -> bf16 hi/lo directly (Q pre-scaled into exp2 domain)
    const float qscale = 0.125f * LOG2E;
    gemm_mma<<<dim3(HID / GBN,  MTOK / GBM), 256>>>(xh, xl, wqh, wql, bq,
                                                    nullptr, qh, ql, qscale, MTOK, HID,  HID);
    gemm_mma<<<dim3(KVSZ / GBN, MTOK / GBM), 256>>>(xh, xl, wkh, wkl, bk,
                                                    nullptr, kh, kl, 1.f, MTOK, KVSZ, HID);
    gemm_mma<<<dim3(KVSZ / GBN, MTOK / GBM), 256>>>(xh, xl, wvh, wvl, bv,
                                                    nullptr, vh, vl, 1.f, MTOK, KVSZ, HID);

    // 3) tensor-core flash attention -> bf16 hi/lo
    flash_mma<<<dim3(SEQ / 64, HEADS, BATCH), 128, FSMEM>>>(qh, ql, kh, kl, vh, vl,
                                                            mask, aoh, aol);

    // 4) output projection (fp32 out)
    gemm_mma<<<dim3(HID / GBN, MTOK / GBM), 256>>>(aoh, aol, woh, wol, bo,
                                                   out, nullptr, nullptr, 1.f, MTOK, HID, HID);
}